// round 13
// baseline (speedup 1.0000x reference)
#include <cuda_runtime.h>
#include <cstdint>

// Problem constants: B=64, MEL_MAX=2000, TEXT_MAX=256, g=0.2
#define BATCH   64
#define MEL_MAX 2000
#define TXT_MAX 256
#define A_COEF  12.5f            // 1/(2 g^2)

#define SLABS   16               // t-slabs per batch
#define SLAB    125              // rows per slab (16*125 = 2000)
#define NBLK    (SLABS * BATCH)  // 1024 blocks
#define NTHR    256              // 8 warps; warp strides t by 8 within slab

#define NSTAGE  6                // cp.async ring depth (prefetch distance 5)
#define PFD     5

typedef unsigned long long u64;

// Scratch (__device__ globals — no allocation allowed)
__device__ double       g_block[NBLK];
__device__ unsigned int g_count = 0;

// ---- packed f32x2 helpers (Blackwell) ----
__device__ __forceinline__ u64 pk2(float lo, float hi) {
    u64 r; asm("mov.b64 %0,{%1,%2};" : "=l"(r) : "f"(lo), "f"(hi)); return r;
}
__device__ __forceinline__ void unpk2(u64 a, float& lo, float& hi) {
    asm("mov.b64 {%0,%1},%2;" : "=f"(lo), "=f"(hi) : "l"(a));
}
__device__ __forceinline__ u64 mul2(u64 a, u64 b) {
    u64 r; asm("mul.rn.f32x2 %0,%1,%2;" : "=l"(r) : "l"(a), "l"(b)); return r;
}
__device__ __forceinline__ u64 add2(u64 a, u64 b) {
    u64 r; asm("add.rn.f32x2 %0,%1,%2;" : "=l"(r) : "l"(a), "l"(b)); return r;
}
__device__ __forceinline__ u64 fma2(u64 a, u64 b, u64 c) {
    u64 r; asm("fma.rn.f32x2 %0,%1,%2,%3;" : "=l"(r) : "l"(a), "l"(b), "l"(c)); return r;
}

// ---- cp.async helpers ----
__device__ __forceinline__ uint32_t smem_u32(const void* p) {
    uint32_t a;
    asm("{ .reg .u64 t; cvta.to.shared.u64 t, %1; cvt.u32.u64 %0, t; }"
        : "=r"(a) : "l"(p));
    return a;
}
__device__ __forceinline__ void cpa16(uint32_t saddr, const float* g, bool p) {
    asm volatile(
        "{\n\t.reg .pred q;\n\tsetp.ne.u32 q,%0,0;\n\t"
        "@q cp.async.cg.shared.global [%1],[%2],16;\n\t}"
        :: "r"((int)p), "r"(saddr), "l"(g));
}
#define CPA_COMMIT() asm volatile("cp.async.commit_group;" ::: "memory")
#define CPA_WAIT(n)  asm volatile("cp.async.wait_group %0;" :: "n"(n) : "memory")

// ---------------------------------------------------------------------------
// Fused kernel, slab-balanced, cp.async per-lane pipeline (depth 6):
// in-flight bytes live in SMEM, not registers. Block (x,b) owns t in
// [125x, min(125(x+1),ml)); warp w: t = 125x + w + 8k. Lane owns 8
// contiguous text positions. No lane reads another lane's smem slot, so
// the pipeline needs no barriers. Gaussian recurrent in both axes.
// Last block (atomic ticket) finalizes.
// ---------------------------------------------------------------------------
__global__ __launch_bounds__(NTHR, 4) void fused_kernel(
    const float* __restrict__ pred,
    const int*   __restrict__ tlen,
    const int*   __restrict__ mlen,
    float*       __restrict__ out)
{
    // [warp][stage][256 floats]: per-stage 1KB = 32 lanes * (16B lo + 16B hi)
    __shared__ float sbuf[8][NSTAGE][256];

    const int lane = threadIdx.x & 31;
    const int wid  = threadIdx.x >> 5;
    const int b    = blockIdx.y;
    const int x    = blockIdx.x;

    const int ml    = __ldg(&mlen[b]);
    const int tbase = x * SLAB;

    u64 sP = 0, sE = 0;   // packed accumulators: sum p, sum E*p

    if (tbase < ml) {
        const int tl   = __ldg(&tlen[b]);
        const int tend = (tbase + SLAB < ml) ? tbase + SLAB : ml;

        // ---- loop-invariant constants ----
        const float inv_tl = 1.0f / (float)tl;
        const float inv_ml = 1.0f / (float)ml;
        const int   n0     = lane * 8;
        const float alpha0 = (float)n0 * inv_tl;
        const float ca     = 2.0f * A_COEF * inv_tl * inv_ml;
        const float cb     = -A_COEF * inv_tl * inv_tl * (float)(2 * n0 + 1);
        const float q2     = __expf(-2.0f * A_COEF * inv_tl * inv_tl);
        const float q2sq   = q2 * q2;
        const float q8     = q2sq * q2sq;
        const u64   Q4     = pk2(q8, q8);

        int count = tl - n0; if (count < 0) count = 0; if (count > 8) count = 8;
        const bool pred_lo = (count > 0);
        const bool pred_hi = (count > 4);
        const u64 mk0 = pk2(count > 0 ? 1.0f : 0.0f, count > 1 ? 1.0f : 0.0f);
        const u64 mk1 = pk2(count > 2 ? 1.0f : 0.0f, count > 3 ? 1.0f : 0.0f);
        const u64 mk2 = pk2(count > 4 ? 1.0f : 0.0f, count > 5 ? 1.0f : 0.0f);
        const u64 mk3 = pk2(count > 6 ? 1.0f : 0.0f, count > 7 ? 1.0f : 0.0f);

        // ---- t-direction seed recurrence (stride 8) ----
        const int   t0  = tbase + wid;
        const float di  = 8.0f * inv_ml;
        const float u0v = alpha0 - (float)t0 * inv_ml;
        float S  = __expf(-2.0f * A_COEF * di * di);
        float E0 = __expf(-A_COEF * u0v * u0v);
        float rr = __expf(2.0f * A_COEF * di * u0v - A_COEF * di * di);
        float m0 = __expf(fmaf(ca, (float)t0, cb));
        float RM = __expf(8.0f * ca);
        if (!pred_lo) { E0 = 0.0f; rr = 0.0f; m0 = 0.0f; RM = 0.0f; }

        // number of rows this warp processes (stride 8)
        const int nrows = (t0 < tend) ? ((tend - t0 + 7) >> 3) : 0;

        // ---- per-lane smem slots (no cross-lane reads -> no barriers) ----
        const uint32_t sb = smem_u32(&sbuf[wid][0][0]) + (uint32_t)lane * 16u;
        // stage s: lo at sb + s*1024, hi at sb + s*1024 + 512

        // zero-fill own slots once (lanes whose cp.asyncs are predicated
        // off will read exact zeros; masks make them contribute 0)
        {
            float4 z = make_float4(0.f, 0.f, 0.f, 0.f);
            #pragma unroll
            for (int sidx = 0; sidx < NSTAGE; sidx++) {
                *(float4*)(&sbuf[wid][sidx][lane * 4])       = z;
                *(float4*)(&sbuf[wid][sidx][128 + lane * 4]) = z;
            }
        }

        const float* rowp  = pred + (size_t)b * (MEL_MAX * TXT_MAX)
                                  + (size_t)t0 * TXT_MAX + n0;
        const size_t rstep = (size_t)8 * TXT_MAX;   // 8 rows ahead per k

        // ---- prologue: prefetch rows 0..PFD-1 ----
        #pragma unroll
        for (int j = 0; j < PFD; j++) {
            const bool rv = (j < nrows);
            const uint32_t st = sb + (uint32_t)j * 1024u;
            cpa16(st,        rowp + (size_t)j * rstep,     rv && pred_lo);
            cpa16(st + 512u, rowp + (size_t)j * rstep + 4, rv && pred_hi);
            CPA_COMMIT();
        }

        // ---- main loop: consume row k, prefetch row k+PFD ----
        int cons = 0;                 // consume stage
        int prod = PFD;               // produce stage
        const float* pfp = rowp + (size_t)PFD * rstep;
        for (int k = 0; k < nrows; k++) {
            {   // prefetch
                const bool rv = (k + PFD < nrows);
                const uint32_t st = sb + (uint32_t)prod * 1024u;
                cpa16(st,        pfp,     rv && pred_lo);
                cpa16(st + 512u, pfp + 4, rv && pred_hi);
                CPA_COMMIT();
                if (++prod == NSTAGE) prod = 0;
                pfp += rstep;
            }
            CPA_WAIT(PFD);            // row k's group complete

            const float4 flo = *(const float4*)(&sbuf[wid][cons][lane * 4]);
            const float4 fhi = *(const float4*)(&sbuf[wid][cons][128 + lane * 4]);
            if (++cons == NSTAGE) cons = 0;

            const u64 lx = pk2(flo.x, flo.y);
            const u64 ly = pk2(flo.z, flo.w);
            const u64 hx = pk2(fhi.x, fhi.y);
            const u64 hy = pk2(fhi.z, fhi.w);

            // column chain (packed even/odd recurrence)
            const float ms = m0 * m0;
            const float m2 = ms * q2;
            u64 E2 = pk2(E0, E0 * m0);
            u64 M2 = pk2(m2, m2 * q2sq);
            u64 mp;
            mp = mul2(lx, mk0); sP = add2(sP, mp); sE = fma2(E2, mp, sE);
            E2 = mul2(E2, M2); M2 = mul2(M2, Q4);
            mp = mul2(ly, mk1); sP = add2(sP, mp); sE = fma2(E2, mp, sE);
            E2 = mul2(E2, M2); M2 = mul2(M2, Q4);
            mp = mul2(hx, mk2); sP = add2(sP, mp); sE = fma2(E2, mp, sE);
            E2 = mul2(E2, M2);
            mp = mul2(hy, mk3); sP = add2(sP, mp); sE = fma2(E2, mp, sE);

            // advance t-direction seeds
            E0 *= rr; rr *= S; m0 *= RM;
        }
        CPA_WAIT(0);                  // drain before any smem reuse
    }

    // ---- combine: loss = sum p - sum E p ----
    float x0, x1, y0, y1;
    unpk2(sP, x0, x1);
    unpk2(sE, y0, y1);
    float tot = (x0 + x1) - (y0 + y1);

    #pragma unroll
    for (int o = 16; o > 0; o >>= 1)
        tot += __shfl_xor_sync(0xFFFFFFFFu, tot, o);

    __shared__ double wsum[8];
    if (lane == 0) wsum[wid] = (double)tot;
    __syncthreads();

    __shared__ bool amLast;
    const int bid = blockIdx.y * SLABS + blockIdx.x;
    if (threadIdx.x == 0) {
        double sacc = 0.0;
        #pragma unroll
        for (int k = 0; k < 8; k++) sacc += wsum[k];
        g_block[bid] = sacc;
        __threadfence();
        amLast = (atomicAdd(&g_count, 1u) == NBLK - 1);
    }
    __syncthreads();

    // ---- last block: final reduction + normalizer ----
    if (amLast) {
        __threadfence();
        double sv = 0.0;
        for (int k = threadIdx.x; k < NBLK; k += NTHR)
            sv += __ldcg(&g_block[k]);
        double sa = 0.0;
        if (threadIdx.x < BATCH)
            sa = (double)__ldg(&tlen[threadIdx.x]) * (double)__ldg(&mlen[threadIdx.x]);

        #pragma unroll
        for (int o = 16; o > 0; o >>= 1) {
            sv += __shfl_xor_sync(0xFFFFFFFFu, sv, o);
            sa += __shfl_xor_sync(0xFFFFFFFFu, sa, o);
        }

        __shared__ double fv[8], fa[8];
        if (lane == 0) { fv[wid] = sv; fa[wid] = sa; }
        __syncthreads();

        if (threadIdx.x == 0) {
            double tv = 0.0, ta = 0.0;
            #pragma unroll
            for (int k = 0; k < 8; k++) { tv += fv[k]; ta += fa[k]; }
            out[0] = (float)(tv / ta);   // attention_weight = 1.0
            g_count = 0;                 // reset for next graph replay
        }
    }
}

// ---------------------------------------------------------------------------
// Inputs (metadata order): targets (unused), predictions, text_lengths,
// mel_lengths. Output: single float.
// ---------------------------------------------------------------------------
extern "C" void kernel_launch(void* const* d_in, const int* in_sizes, int n_in,
                              void* d_out, int out_size)
{
    (void)in_sizes; (void)n_in; (void)out_size;
    const float* pred = (const float*)d_in[1];
    const int*   tlen = (const int*)d_in[2];
    const int*   mlen = (const int*)d_in[3];
    float*       out  = (float*)d_out;

    dim3 grid(SLABS, BATCH);
    fused_kernel<<<grid, NTHR>>>(pred, tlen, mlen, out);
}